// round 1
// baseline (speedup 1.0000x reference)
#include <cuda_runtime.h>
#include <cuda_bf16.h>
#include <math.h>

// Problem constants
#define B_ 4
#define N_ 2048
#define C_ 1024
#define M_TOT (B_ * N_)   // 8192

// Scratch for Q, K, V projections (allocation-free: __device__ globals)
__device__ float g_Q[(size_t)M_TOT * C_];
__device__ float g_K[(size_t)M_TOT * C_];
__device__ float g_V[(size_t)M_TOT * C_];

#define BM 128
#define BN 128
#define BK 16
#define TM 8
#define TN 8

// C[m][n] = alpha * sum_k A[m][k] * B[n][k]  (+ bias[n])
// A: [M,K] row-major, B: [Nn,K] row-major (i.e. A @ B^T)
__global__ __launch_bounds__(256) void gemm_nt(
    const float* __restrict__ A, const float* __restrict__ Bm,
    const float* __restrict__ bias, float* __restrict__ Cm,
    int M, int Nn, int K, float alpha,
    long strideA, long strideB, long strideC)
{
    const long bz = blockIdx.z;
    A  += bz * strideA;
    Bm += bz * strideB;
    Cm += bz * strideC;

    __shared__ float As[BK][BM];
    __shared__ float Bs[BK][BN];

    const int tid = threadIdx.x;
    const int m0 = blockIdx.y * BM;
    const int n0 = blockIdx.x * BN;
    const int ty = tid >> 4;   // 0..15
    const int tx = tid & 15;   // 0..15

    float acc[TM][TN];
    #pragma unroll
    for (int i = 0; i < TM; i++)
        #pragma unroll
        for (int j = 0; j < TN; j++) acc[i][j] = 0.f;

    for (int k0 = 0; k0 < K; k0 += BK) {
        // Load A tile (BM x BK), store transposed: 512 float4, 2 per thread
        #pragma unroll
        for (int r = 0; r < 2; r++) {
            int q   = tid + r * 256;
            int row = q >> 2;
            int c4  = (q & 3) * 4;
            float4 v = *(const float4*)&A[(long)(m0 + row) * K + k0 + c4];
            As[c4 + 0][row] = v.x; As[c4 + 1][row] = v.y;
            As[c4 + 2][row] = v.z; As[c4 + 3][row] = v.w;
        }
        // Load B tile (BN x BK), store transposed
        #pragma unroll
        for (int r = 0; r < 2; r++) {
            int q   = tid + r * 256;
            int row = q >> 2;
            int c4  = (q & 3) * 4;
            float4 v = *(const float4*)&Bm[(long)(n0 + row) * K + k0 + c4];
            Bs[c4 + 0][row] = v.x; Bs[c4 + 1][row] = v.y;
            Bs[c4 + 2][row] = v.z; Bs[c4 + 3][row] = v.w;
        }
        __syncthreads();

        #pragma unroll
        for (int k = 0; k < BK; k++) {
            float a[TM], b[TN];
            #pragma unroll
            for (int i = 0; i < TM; i++) a[i] = As[k][ty * TM + i];
            #pragma unroll
            for (int j = 0; j < TN; j++) b[j] = Bs[k][tx * TN + j];
            #pragma unroll
            for (int i = 0; i < TM; i++)
                #pragma unroll
                for (int j = 0; j < TN; j++)
                    acc[i][j] += a[i] * b[j];
        }
        __syncthreads();
    }

    #pragma unroll
    for (int i = 0; i < TM; i++) {
        int gm = m0 + ty * TM + i;
        #pragma unroll
        for (int j = 0; j < TN; j += 4) {
            int gn = n0 + tx * TN + j;
            float4 v;
            v.x = acc[i][j + 0] * alpha;
            v.y = acc[i][j + 1] * alpha;
            v.z = acc[i][j + 2] * alpha;
            v.w = acc[i][j + 3] * alpha;
            if (bias) {
                v.x += bias[gn + 0]; v.y += bias[gn + 1];
                v.z += bias[gn + 2]; v.w += bias[gn + 3];
            }
            *(float4*)&Cm[(long)gm * Nn + gn] = v;
        }
    }
}

// C[m][n] = sum_k A[m][k] * B[k][n]   (A @ B, B row-major [K,Nn])
__global__ __launch_bounds__(256) void gemm_nn(
    const float* __restrict__ A, const float* __restrict__ Bm,
    float* __restrict__ Cm,
    int M, int Nn, int K,
    long strideA, long strideB, long strideC)
{
    const long bz = blockIdx.z;
    A  += bz * strideA;
    Bm += bz * strideB;
    Cm += bz * strideC;

    __shared__ float As[BK][BM];
    __shared__ float Bs[BK][BN];

    const int tid = threadIdx.x;
    const int m0 = blockIdx.y * BM;
    const int n0 = blockIdx.x * BN;
    const int ty = tid >> 4;
    const int tx = tid & 15;

    float acc[TM][TN];
    #pragma unroll
    for (int i = 0; i < TM; i++)
        #pragma unroll
        for (int j = 0; j < TN; j++) acc[i][j] = 0.f;

    for (int k0 = 0; k0 < K; k0 += BK) {
        #pragma unroll
        for (int r = 0; r < 2; r++) {
            int q   = tid + r * 256;
            int row = q >> 2;
            int c4  = (q & 3) * 4;
            float4 v = *(const float4*)&A[(long)(m0 + row) * K + k0 + c4];
            As[c4 + 0][row] = v.x; As[c4 + 1][row] = v.y;
            As[c4 + 2][row] = v.z; As[c4 + 3][row] = v.w;
        }
        // B tile: BK rows x BN cols, direct layout (coalesced)
        #pragma unroll
        for (int r = 0; r < 2; r++) {
            int q   = tid + r * 256;
            int row = q >> 5;          // 0..15
            int c4  = (q & 31) * 4;    // 0..124
            float4 v = *(const float4*)&Bm[(long)(k0 + row) * Nn + n0 + c4];
            *(float4*)&Bs[row][c4] = v;
        }
        __syncthreads();

        #pragma unroll
        for (int k = 0; k < BK; k++) {
            float a[TM], b[TN];
            #pragma unroll
            for (int i = 0; i < TM; i++) a[i] = As[k][ty * TM + i];
            #pragma unroll
            for (int j = 0; j < TN; j++) b[j] = Bs[k][tx * TN + j];
            #pragma unroll
            for (int i = 0; i < TM; i++)
                #pragma unroll
                for (int j = 0; j < TN; j++)
                    acc[i][j] += a[i] * b[j];
        }
        __syncthreads();
    }

    #pragma unroll
    for (int i = 0; i < TM; i++) {
        int gm = m0 + ty * TM + i;
        #pragma unroll
        for (int j = 0; j < TN; j += 4) {
            int gn = n0 + tx * TN + j;
            float4 v;
            v.x = acc[i][j + 0]; v.y = acc[i][j + 1];
            v.z = acc[i][j + 2]; v.w = acc[i][j + 3];
            *(float4*)&Cm[(long)gm * Nn + gn] = v;
        }
    }
}

// In-place softmax over rows of length L=2048. One block (256 threads) per row.
__global__ __launch_bounds__(256) void softmax_rows(float* __restrict__ P, int L)
{
    long row = blockIdx.x;
    float* p = P + row * (long)L;
    const int tid  = threadIdx.x;
    const int lane = tid & 31;
    const int warp = tid >> 5;

    float vals[8];
    float m = -INFINITY;
    #pragma unroll
    for (int i = 0; i < 8; i++) {
        vals[i] = p[tid + i * 256];
        m = fmaxf(m, vals[i]);
    }

    __shared__ float redmax[8];
    __shared__ float redsum[8];

    #pragma unroll
    for (int off = 16; off > 0; off >>= 1)
        m = fmaxf(m, __shfl_xor_sync(0xffffffffu, m, off));
    if (lane == 0) redmax[warp] = m;
    __syncthreads();
    float rowmax = redmax[0];
    #pragma unroll
    for (int w = 1; w < 8; w++) rowmax = fmaxf(rowmax, redmax[w]);

    float s = 0.f;
    #pragma unroll
    for (int i = 0; i < 8; i++) {
        vals[i] = expf(vals[i] - rowmax);
        s += vals[i];
    }
    #pragma unroll
    for (int off = 16; off > 0; off >>= 1)
        s += __shfl_xor_sync(0xffffffffu, s, off);
    if (lane == 0) redsum[warp] = s;
    __syncthreads();
    float total = 0.f;
    #pragma unroll
    for (int w = 0; w < 8; w++) total += redsum[w];

    float inv = 1.f / total;
    #pragma unroll
    for (int i = 0; i < 8; i++)
        p[tid + i * 256] = vals[i] * inv;
}

extern "C" void kernel_launch(void* const* d_in, const int* in_sizes, int n_in,
                              void* d_out, int out_size)
{
    const float* h  = (const float*)d_in[0];  // [B,N,C]
    const float* Wq = (const float*)d_in[1];  // [C,C]
    const float* bq = (const float*)d_in[2];
    const float* Wk = (const float*)d_in[3];
    const float* bk = (const float*)d_in[4];
    const float* Wv = (const float*)d_in[5];
    const float* bv = (const float*)d_in[6];

    float* out  = (float*)d_out;                          // [B,N,C]
    float* attn = out + (long)B_ * N_ * C_;               // [B,N,N]

    float *Q, *Kp, *V;
    cudaGetSymbolAddress((void**)&Q,  g_Q);
    cudaGetSymbolAddress((void**)&Kp, g_K);
    cudaGetSymbolAddress((void**)&V,  g_V);

    dim3 blk(256);

    // 1) QKV projections: [8192,1024] = h @ W^T + b
    dim3 g1(C_ / BN, M_TOT / BM, 1);
    gemm_nt<<<g1, blk>>>(h, Wq, bq, Q,  M_TOT, C_, C_, 1.f, 0, 0, 0);
    gemm_nt<<<g1, blk>>>(h, Wk, bk, Kp, M_TOT, C_, C_, 1.f, 0, 0, 0);
    gemm_nt<<<g1, blk>>>(h, Wv, bv, V,  M_TOT, C_, C_, 1.f, 0, 0, 0);

    // 2) scores = Q @ K^T * 1/sqrt(d), per batch
    dim3 g2(N_ / BN, N_ / BM, B_);
    const float scale = 1.f / 32.f;  // 1/sqrt(1024)
    gemm_nt<<<g2, blk>>>(Q, Kp, nullptr, attn, N_, N_, C_, scale,
                         (long)N_ * C_, (long)N_ * C_, (long)N_ * N_);

    // 3) softmax rows (in place on attn output)
    softmax_rows<<<B_ * N_, blk>>>(attn, N_);

    // 4) out = attn @ V, per batch
    dim3 g3(C_ / BN, N_ / BM, B_);
    gemm_nn<<<g3, blk>>>(attn, V, out, N_, C_, N_,
                         (long)N_ * N_, (long)N_ * C_, (long)N_ * C_);
}

// round 3
// speedup vs baseline: 2.5341x; 2.5341x over previous
#include <cuda_runtime.h>
#include <cuda_bf16.h>
#include <math.h>
#include <stdint.h>

#define B_ 4
#define N_ 2048
#define C_ 1024
#define M_TOT (B_ * N_)   // 8192

// ---------------- scratch (__device__ globals; no allocation) ----------------
__device__ __align__(128) __nv_bfloat16 g_h_hi[(size_t)M_TOT * C_];
__device__ __align__(128) __nv_bfloat16 g_h_lo[(size_t)M_TOT * C_];
__device__ __align__(128) __nv_bfloat16 g_Wq_hi[C_ * C_], g_Wq_lo[C_ * C_];
__device__ __align__(128) __nv_bfloat16 g_Wk_hi[C_ * C_], g_Wk_lo[C_ * C_];
__device__ __align__(128) __nv_bfloat16 g_Wv_hi[C_ * C_], g_Wv_lo[C_ * C_];
__device__ __align__(128) __nv_bfloat16 g_Q_hi[(size_t)M_TOT * C_], g_Q_lo[(size_t)M_TOT * C_];
__device__ __align__(128) __nv_bfloat16 g_K_hi[(size_t)M_TOT * C_], g_K_lo[(size_t)M_TOT * C_];
__device__ __align__(128) __nv_bfloat16 g_VT_hi[(size_t)C_ * M_TOT], g_VT_lo[(size_t)C_ * M_TOT];
__device__ __align__(128) __nv_bfloat16 g_P_hi[(size_t)B_ * N_ * N_], g_P_lo[(size_t)B_ * N_ * N_];

// ---------------- portable PTX helpers (base-target safe) ----------------
__device__ __forceinline__ uint32_t smem_u32(const void* p) {
    uint32_t a;
    asm("{ .reg .u64 t; cvta.to.shared.u64 t, %1; cvt.u32.u64 %0, t; }" : "=r"(a) : "l"(p));
    return a;
}
__device__ __forceinline__ void cp_async16(uint32_t dst, const void* src) {
    asm volatile("cp.async.cg.shared.global [%0], [%1], 16;" :: "r"(dst), "l"(src) : "memory");
}
#define CP_COMMIT()  asm volatile("cp.async.commit_group;" ::: "memory")
#define CP_WAIT(n)   asm volatile("cp.async.wait_group %0;" :: "n"(n) : "memory")

__device__ __forceinline__ void ldsm_x4(uint32_t& r0, uint32_t& r1, uint32_t& r2, uint32_t& r3,
                                        uint32_t addr) {
    asm volatile("ldmatrix.sync.aligned.m8n8.x4.shared.b16 {%0,%1,%2,%3}, [%4];"
                 : "=r"(r0), "=r"(r1), "=r"(r2), "=r"(r3) : "r"(addr));
}
__device__ __forceinline__ void mma16816(float* d, const uint32_t* a, const uint32_t* b) {
    asm volatile(
        "mma.sync.aligned.m16n8k16.row.col.f32.bf16.bf16.f32 "
        "{%0,%1,%2,%3}, {%4,%5,%6,%7}, {%8,%9}, {%0,%1,%2,%3};"
        : "+f"(d[0]), "+f"(d[1]), "+f"(d[2]), "+f"(d[3])
        : "r"(a[0]), "r"(a[1]), "r"(a[2]), "r"(a[3]), "r"(b[0]), "r"(b[1]));
}
__device__ __forceinline__ uint32_t swz(uint32_t off) { return off ^ ((off >> 3) & 0x70); }

// ---------------- bf16x3 HMMA GEMM: D = alpha*(Ah@Bh^T + Ah@Bl^T + Al@Bh^T) (+bias) --------
// A: [M,K] hi/lo bf16 (lda). B: [N,K] hi/lo bf16 (ldb). 128x128 block tile, BK=64.
// Output fp32 (Cf) or bf16 hi/lo (Chi/Clo). bias_mode: 0 none, 1 per-col, 2 per-row.
#define BM_ 128
#define BN_ 128
#define STAGES 3
#define TILE_BYTES 16384          // 128 rows * 128 B
#define STAGE_BYTES 32768         // A + B
#define SMEM_GEMM (STAGES * STAGE_BYTES)   // 96 KB

__global__ __launch_bounds__(256, 1) void gemm_bf16x3(
    const __nv_bfloat16* __restrict__ Ah, const __nv_bfloat16* __restrict__ Al,
    const __nv_bfloat16* __restrict__ Bh, const __nv_bfloat16* __restrict__ Bl,
    int lda, int ldb, long long batA, long long batB, int K,
    float* __restrict__ Cf, long long batCf, int ldc,
    __nv_bfloat16* __restrict__ Chi, __nv_bfloat16* __restrict__ Clo, long long batCb,
    float alpha, const float* __restrict__ bias, int bias_mode)
{
    extern __shared__ char smem[];
    const uint32_t sbase = smem_u32(smem);
    const int tid  = threadIdx.x;
    const int wid  = tid >> 5;
    const int lane = tid & 31;
    const long long bz = blockIdx.z;
    const int m0 = blockIdx.y * BM_;
    const int n0 = blockIdx.x * BN_;

    const __nv_bfloat16* A_h = Ah + bz * batA;
    const __nv_bfloat16* A_l = Al + bz * batA;
    const __nv_bfloat16* B_h = Bh + bz * batB;
    const __nv_bfloat16* B_l = Bl + bz * batB;

    // warp tiling: 2 (m) x 4 (n); warp tile 64x32
    const int wm = (wid >> 2) * 64;
    const int wn = (wid & 3) * 32;

    const int nkp = K >> 6;     // K/64 chunks per product term
    const int NK  = 3 * nkp;    // virtual chunks (Ah*Bh, Ah*Bl, Al*Bh)

    // loader indices: 256 threads, 16B chunks; tile = 1024 chunks -> 4 iters
    const int lrow = tid >> 3;       // 0..31
    const int lch  = tid & 7;        // 16B chunk in 128B row

    auto load_stage = [&](int kc, int s) {
        int p  = kc / nkp;
        int kk = kc - p * nkp;
        const __nv_bfloat16* Asrc = (p == 2) ? A_l : A_h;
        const __nv_bfloat16* Bsrc = (p == 1) ? B_l : B_h;
        Asrc += (size_t)m0 * lda + kk * 64;
        Bsrc += (size_t)n0 * ldb + kk * 64;
        const uint32_t sa = sbase + s * STAGE_BYTES;
        const uint32_t sb = sa + TILE_BYTES;
        #pragma unroll
        for (int r = 0; r < 4; r++) {
            int row = r * 32 + lrow;
            uint32_t sw = swz(row * 128 + lch * 16);
            cp_async16(sa + sw, Asrc + (size_t)row * lda + lch * 8);
        }
        #pragma unroll
        for (int r = 0; r < 4; r++) {
            int row = r * 32 + lrow;
            uint32_t sw = swz(row * 128 + lch * 16);
            cp_async16(sb + sw, Bsrc + (size_t)row * ldb + lch * 8);
        }
        CP_COMMIT();
    };

    float acc[4][4][4];
    #pragma unroll
    for (int i = 0; i < 4; i++)
        #pragma unroll
        for (int j = 0; j < 4; j++)
            #pragma unroll
            for (int e = 0; e < 4; e++) acc[i][j][e] = 0.f;

    // ldmatrix per-lane address components
    const int a_row_l = ((lane >> 3) & 1) * 8 + (lane & 7);
    const int a_col_l = ((lane >> 4) & 1) * 16;           // bytes
    const int b_row_l = ((lane >> 4) & 1) * 8 + (lane & 7);
    const int b_col_l = ((lane >> 3) & 1) * 16;           // bytes

    // prologue
    #pragma unroll
    for (int i = 0; i < STAGES; i++) load_stage(i, i);

    int s = 0;
    for (int kc = 0; kc < NK; kc++) {
        CP_WAIT(STAGES - 1);
        __syncthreads();

        const uint32_t sa = sbase + s * STAGE_BYTES;
        const uint32_t sb = sa + TILE_BYTES;

        #pragma unroll
        for (int k16 = 0; k16 < 4; k16++) {
            uint32_t a[4][4];
            uint32_t b[4][2];
            #pragma unroll
            for (int mt = 0; mt < 4; mt++) {
                uint32_t off = (uint32_t)(wm + mt * 16 + a_row_l) * 128 + k16 * 32 + a_col_l;
                ldsm_x4(a[mt][0], a[mt][1], a[mt][2], a[mt][3], sa + swz(off));
            }
            #pragma unroll
            for (int nt2 = 0; nt2 < 2; nt2++) {
                uint32_t off = (uint32_t)(wn + nt2 * 16 + b_row_l) * 128 + k16 * 32 + b_col_l;
                uint32_t r0, r1, r2, r3;
                ldsm_x4(r0, r1, r2, r3, sb + swz(off));
                b[nt2 * 2 + 0][0] = r0; b[nt2 * 2 + 0][1] = r1;
                b[nt2 * 2 + 1][0] = r2; b[nt2 * 2 + 1][1] = r3;
            }
            #pragma unroll
            for (int mt = 0; mt < 4; mt++)
                #pragma unroll
                for (int nt = 0; nt < 4; nt++)
                    mma16816(acc[mt][nt], a[mt], b[nt]);
        }

        __syncthreads();
        if (kc + STAGES < NK) load_stage(kc + STAGES, s);
        s++;
        if (s == STAGES) s = 0;
    }

    // ---------------- epilogue ----------------
    const int erow = lane >> 2;         // 0..7
    const int ecol = (lane & 3) * 2;    // 0,2,4,6

    #pragma unroll
    for (int mt = 0; mt < 4; mt++) {
        #pragma unroll
        for (int h = 0; h < 2; h++) {   // row / row+8 halves of the m16 tile
            const int gm = m0 + wm + mt * 16 + h * 8 + erow;
            float brow = (bias_mode == 2) ? bias[gm] : 0.f;
            #pragma unroll
            for (int nt = 0; nt < 4; nt++) {
                const int gn = n0 + wn + nt * 8 + ecol;
                float x0 = acc[mt][nt][h * 2 + 0] * alpha;
                float x1 = acc[mt][nt][h * 2 + 1] * alpha;
                if (bias_mode == 1) { x0 += bias[gn]; x1 += bias[gn + 1]; }
                else if (bias_mode == 2) { x0 += brow; x1 += brow; }
                if (Cf) {
                    float2 v; v.x = x0; v.y = x1;
                    *(float2*)(Cf + bz * batCf + (size_t)gm * ldc + gn) = v;
                } else {
                    __nv_bfloat16 h0 = __float2bfloat16(x0);
                    __nv_bfloat16 h1 = __float2bfloat16(x1);
                    __nv_bfloat16 l0 = __float2bfloat16(x0 - __bfloat162float(h0));
                    __nv_bfloat16 l1 = __float2bfloat16(x1 - __bfloat162float(h1));
                    union { uint32_t u; __nv_bfloat16 hh[2]; } ph, pl;
                    ph.hh[0] = h0; ph.hh[1] = h1;
                    pl.hh[0] = l0; pl.hh[1] = l1;
                    *(uint32_t*)(Chi + bz * batCb + (size_t)gm * ldc + gn) = ph.u;
                    *(uint32_t*)(Clo + bz * batCb + (size_t)gm * ldc + gn) = pl.u;
                }
            }
        }
    }
}

// ---------------- elementwise kernels ----------------
__global__ __launch_bounds__(256) void split_fp32(
    const float* __restrict__ x, __nv_bfloat16* __restrict__ hi,
    __nv_bfloat16* __restrict__ lo, size_t n4)
{
    size_t i = ((size_t)blockIdx.x * blockDim.x + threadIdx.x);
    if (i >= n4) return;
    float4 v = *(const float4*)(x + i * 4);
    float vv[4] = {v.x, v.y, v.z, v.w};
    union { uint2 u; __nv_bfloat16 h[4]; } ph, pl;
    #pragma unroll
    for (int e = 0; e < 4; e++) {
        __nv_bfloat16 h16 = __float2bfloat16(vv[e]);
        ph.h[e] = h16;
        pl.h[e] = __float2bfloat16(vv[e] - __bfloat162float(h16));
    }
    *(uint2*)(hi + i * 4) = ph.u;
    *(uint2*)(lo + i * 4) = pl.u;
}

// softmax over rows of 2048 fp32, in-place, plus bf16 hi/lo split output.
__global__ __launch_bounds__(256) void softmax_split(
    float* __restrict__ P, __nv_bfloat16* __restrict__ Phi, __nv_bfloat16* __restrict__ Plo)
{
    const size_t row = blockIdx.x;
    float* p = P + row * (size_t)N_;
    __nv_bfloat16* ph = Phi + row * (size_t)N_;
    __nv_bfloat16* pl = Plo + row * (size_t)N_;
    const int tid = threadIdx.x;
    const int lane = tid & 31;
    const int warp = tid >> 5;

    float vals[8];
    float m = -INFINITY;
    #pragma unroll
    for (int i = 0; i < 8; i++) {
        vals[i] = p[tid + i * 256];
        m = fmaxf(m, vals[i]);
    }
    __shared__ float redmax[8], redsum[8];
    #pragma unroll
    for (int off = 16; off > 0; off >>= 1)
        m = fmaxf(m, __shfl_xor_sync(0xffffffffu, m, off));
    if (lane == 0) redmax[warp] = m;
    __syncthreads();
    float rowmax = redmax[0];
    #pragma unroll
    for (int w = 1; w < 8; w++) rowmax = fmaxf(rowmax, redmax[w]);

    float sum = 0.f;
    #pragma unroll
    for (int i = 0; i < 8; i++) {
        vals[i] = expf(vals[i] - rowmax);
        sum += vals[i];
    }
    #pragma unroll
    for (int off = 16; off > 0; off >>= 1)
        sum += __shfl_xor_sync(0xffffffffu, sum, off);
    if (lane == 0) redsum[warp] = sum;
    __syncthreads();
    float total = 0.f;
    #pragma unroll
    for (int w = 0; w < 8; w++) total += redsum[w];
    float inv = 1.f / total;

    #pragma unroll
    for (int i = 0; i < 8; i++) {
        float v = vals[i] * inv;
        p[tid + i * 256] = v;
        __nv_bfloat16 hi = __float2bfloat16(v);
        ph[tid + i * 256] = hi;
        pl[tid + i * 256] = __float2bfloat16(v - __bfloat162float(hi));
    }
}

// ---------------- launch ----------------
extern "C" void kernel_launch(void* const* d_in, const int* in_sizes, int n_in,
                              void* d_out, int out_size)
{
    const float* h  = (const float*)d_in[0];
    const float* Wq = (const float*)d_in[1];
    const float* bq = (const float*)d_in[2];
    const float* Wk = (const float*)d_in[3];
    const float* bk = (const float*)d_in[4];
    const float* Wv = (const float*)d_in[5];
    const float* bv = (const float*)d_in[6];

    float* out  = (float*)d_out;                 // [B,N,C]
    float* attn = out + (size_t)B_ * N_ * C_;    // [B,N,N]

    __nv_bfloat16 *h_hi, *h_lo, *Wq_hi, *Wq_lo, *Wk_hi, *Wk_lo, *Wv_hi, *Wv_lo;
    __nv_bfloat16 *Q_hi, *Q_lo, *K_hi, *K_lo, *VT_hi, *VT_lo, *P_hi, *P_lo;
    cudaGetSymbolAddress((void**)&h_hi, g_h_hi);   cudaGetSymbolAddress((void**)&h_lo, g_h_lo);
    cudaGetSymbolAddress((void**)&Wq_hi, g_Wq_hi); cudaGetSymbolAddress((void**)&Wq_lo, g_Wq_lo);
    cudaGetSymbolAddress((void**)&Wk_hi, g_Wk_hi); cudaGetSymbolAddress((void**)&Wk_lo, g_Wk_lo);
    cudaGetSymbolAddress((void**)&Wv_hi, g_Wv_hi); cudaGetSymbolAddress((void**)&Wv_lo, g_Wv_lo);
    cudaGetSymbolAddress((void**)&Q_hi, g_Q_hi);   cudaGetSymbolAddress((void**)&Q_lo, g_Q_lo);
    cudaGetSymbolAddress((void**)&K_hi, g_K_hi);   cudaGetSymbolAddress((void**)&K_lo, g_K_lo);
    cudaGetSymbolAddress((void**)&VT_hi, g_VT_hi); cudaGetSymbolAddress((void**)&VT_lo, g_VT_lo);
    cudaGetSymbolAddress((void**)&P_hi, g_P_hi);   cudaGetSymbolAddress((void**)&P_lo, g_P_lo);

    cudaFuncSetAttribute(gemm_bf16x3, cudaFuncAttributeMaxDynamicSharedMemorySize, SMEM_GEMM);

    // 1) splits
    {
        size_t nh4 = (size_t)M_TOT * C_ / 4;
        split_fp32<<<(unsigned)(nh4 / 256), 256>>>(h, h_hi, h_lo, nh4);
        size_t nw4 = (size_t)C_ * C_ / 4;
        split_fp32<<<(unsigned)(nw4 / 256), 256>>>(Wq, Wq_hi, Wq_lo, nw4);
        split_fp32<<<(unsigned)(nw4 / 256), 256>>>(Wk, Wk_hi, Wk_lo, nw4);
        split_fp32<<<(unsigned)(nw4 / 256), 256>>>(Wv, Wv_hi, Wv_lo, nw4);
    }

    dim3 blk(256);

    // 2) Q/K projections: [8192,1024] x [1024,1024]^T -> bf16 hi/lo
    {
        dim3 g(C_ / BN_, M_TOT / BM_, 1);
        gemm_bf16x3<<<g, blk, SMEM_GEMM>>>(
            h_hi, h_lo, Wq_hi, Wq_lo, C_, C_, 0, 0, C_,
            nullptr, 0, C_, Q_hi, Q_lo, 0, 1.0f, bq, 1);
        gemm_bf16x3<<<g, blk, SMEM_GEMM>>>(
            h_hi, h_lo, Wk_hi, Wk_lo, C_, C_, 0, 0, C_,
            nullptr, 0, C_, K_hi, K_lo, 0, 1.0f, bk, 1);
    }
    // 3) V^T = Wv @ h^T + bv (row bias) -> [C_, M_TOT] bf16 hi/lo
    {
        dim3 g(M_TOT / BN_, C_ / BM_, 1);
        gemm_bf16x3<<<g, blk, SMEM_GEMM>>>(
            Wv_hi, Wv_lo, h_hi, h_lo, C_, C_, 0, 0, C_,
            nullptr, 0, M_TOT, VT_hi, VT_lo, 0, 1.0f, bv, 2);
    }
    // 4) scores = (Q @ K^T) / 32 -> fp32 attn (per batch)
    {
        dim3 g(N_ / BN_, N_ / BM_, B_);
        gemm_bf16x3<<<g, blk, SMEM_GEMM>>>(
            Q_hi, Q_lo, K_hi, K_lo, C_, C_,
            (long long)N_ * C_, (long long)N_ * C_, C_,
            attn, (long long)N_ * N_, N_,
            nullptr, nullptr, 0, 1.0f / 32.0f, nullptr, 0);
    }
    // 5) softmax (in place) + bf16 split
    softmax_split<<<B_ * N_, 256>>>(attn, P_hi, P_lo);

    // 6) out = P @ (V^T)^T (per batch: M=2048, N=1024, K=2048)
    {
        dim3 g(C_ / BN_, N_ / BM_, B_);
        gemm_bf16x3<<<g, blk, SMEM_GEMM>>>(
            P_hi, P_lo, VT_hi, VT_lo, N_, M_TOT,
            (long long)N_ * N_, (long long)N_, N_,
            out, (long long)N_ * C_, C_,
            nullptr, nullptr, 0, 1.0f, nullptr, 0);
    }
}

// round 4
// speedup vs baseline: 2.8584x; 1.1280x over previous
#include <cuda_runtime.h>
#include <cuda_bf16.h>
#include <math.h>
#include <stdint.h>

#define B_ 4
#define N_ 2048
#define C_ 1024
#define M_TOT (B_ * N_)   // 8192

// ---------------- scratch (__device__ globals; no allocation) ----------------
__device__ __align__(128) __nv_bfloat16 g_h_hi[(size_t)M_TOT * C_];
__device__ __align__(128) __nv_bfloat16 g_h_lo[(size_t)M_TOT * C_];
__device__ __align__(128) __nv_bfloat16 g_Wq_hi[C_ * C_], g_Wq_lo[C_ * C_];
__device__ __align__(128) __nv_bfloat16 g_Wk_hi[C_ * C_], g_Wk_lo[C_ * C_];
__device__ __align__(128) __nv_bfloat16 g_Wv_hi[C_ * C_], g_Wv_lo[C_ * C_];
__device__ __align__(128) __nv_bfloat16 g_Q_hi[(size_t)M_TOT * C_], g_Q_lo[(size_t)M_TOT * C_];
__device__ __align__(128) __nv_bfloat16 g_K_hi[(size_t)M_TOT * C_], g_K_lo[(size_t)M_TOT * C_];
__device__ __align__(128) __nv_bfloat16 g_VT_hi[(size_t)C_ * M_TOT], g_VT_lo[(size_t)C_ * M_TOT];
__device__ __align__(128) __nv_bfloat16 g_P_hi[(size_t)B_ * N_ * N_], g_P_lo[(size_t)B_ * N_ * N_];

// ---------------- portable PTX helpers (base-target safe) ----------------
__device__ __forceinline__ uint32_t smem_u32(const void* p) {
    uint32_t a;
    asm("{ .reg .u64 t; cvta.to.shared.u64 t, %1; cvt.u32.u64 %0, t; }" : "=r"(a) : "l"(p));
    return a;
}
__device__ __forceinline__ void cp_async16(uint32_t dst, const void* src) {
    asm volatile("cp.async.cg.shared.global [%0], [%1], 16;" :: "r"(dst), "l"(src) : "memory");
}
#define CP_COMMIT()  asm volatile("cp.async.commit_group;" ::: "memory")
#define CP_WAIT(n)   asm volatile("cp.async.wait_group %0;" :: "n"(n) : "memory")

__device__ __forceinline__ void ldsm_x4(uint32_t& r0, uint32_t& r1, uint32_t& r2, uint32_t& r3,
                                        uint32_t addr) {
    asm volatile("ldmatrix.sync.aligned.m8n8.x4.shared.b16 {%0,%1,%2,%3}, [%4];"
                 : "=r"(r0), "=r"(r1), "=r"(r2), "=r"(r3) : "r"(addr));
}
__device__ __forceinline__ void mma16816(float* d, const uint32_t* a, const uint32_t* b) {
    asm volatile(
        "mma.sync.aligned.m16n8k16.row.col.f32.bf16.bf16.f32 "
        "{%0,%1,%2,%3}, {%4,%5,%6,%7}, {%8,%9}, {%0,%1,%2,%3};"
        : "+f"(d[0]), "+f"(d[1]), "+f"(d[2]), "+f"(d[3])
        : "r"(a[0]), "r"(a[1]), "r"(a[2]), "r"(a[3]), "r"(b[0]), "r"(b[1]));
}
__device__ __forceinline__ uint32_t swz(uint32_t off) { return off ^ ((off >> 3) & 0x70); }

// ---------------- bf16x3 HMMA GEMM: D = alpha*(Ah@Bh^T + Ah@Bl^T + Al@Bh^T) (+bias) --------
// A: [M,K] hi/lo bf16 (lda). B: [N,K] hi/lo bf16 (ldb). Block tile 128x256, BK=64.
// 8 warps as 2(m) x 4(n); warp tile 64x64.
// Output fp32 (Cf) or bf16 hi/lo (Chi/Clo). bias_mode: 0 none, 1 per-col, 2 per-row.
#define BM_ 128
#define BN_ 256
#define STAGES 3
#define TILE_A_BYTES 16384         // 128 rows * 128 B
#define TILE_B_BYTES 32768         // 256 rows * 128 B
#define STAGE_BYTES  49152
#define SMEM_GEMM (STAGES * STAGE_BYTES)   // 144 KB

__global__ __launch_bounds__(256, 1) void gemm_bf16x3(
    const __nv_bfloat16* __restrict__ Ah, const __nv_bfloat16* __restrict__ Al,
    const __nv_bfloat16* __restrict__ Bh, const __nv_bfloat16* __restrict__ Bl,
    int lda, int ldb, long long batA, long long batB, int K,
    float* __restrict__ Cf, long long batCf, int ldc,
    __nv_bfloat16* __restrict__ Chi, __nv_bfloat16* __restrict__ Clo, long long batCb,
    float alpha, const float* __restrict__ bias, int bias_mode)
{
    extern __shared__ char smem[];
    const uint32_t sbase = smem_u32(smem);
    const int tid  = threadIdx.x;
    const int wid  = tid >> 5;
    const int lane = tid & 31;
    const long long bz = blockIdx.z;
    const int m0 = blockIdx.y * BM_;
    const int n0 = blockIdx.x * BN_;

    const __nv_bfloat16* A_h = Ah + bz * batA;
    const __nv_bfloat16* A_l = Al + bz * batA;
    const __nv_bfloat16* B_h = Bh + bz * batB;
    const __nv_bfloat16* B_l = Bl + bz * batB;

    // warp tiling: 2 (m) x 4 (n); warp tile 64x64
    const int wm = (wid >> 2) * 64;
    const int wn = (wid & 3) * 64;

    const int nkp = K >> 6;     // K/64 chunks per product term
    const int NK  = 3 * nkp;    // virtual chunks (Ah*Bh, Ah*Bl, Al*Bh)

    // loader indices: 256 threads, 16B chunks (8 per 128B row)
    const int lrow = tid >> 3;       // 0..31
    const int lch  = tid & 7;

    auto load_stage = [&](int kc, int s) {
        int p  = kc / nkp;
        int kk = kc - p * nkp;
        const __nv_bfloat16* Asrc = (p == 2) ? A_l : A_h;
        const __nv_bfloat16* Bsrc = (p == 1) ? B_l : B_h;
        Asrc += (size_t)m0 * lda + kk * 64;
        Bsrc += (size_t)n0 * ldb + kk * 64;
        const uint32_t sa = sbase + s * STAGE_BYTES;
        const uint32_t sb = sa + TILE_A_BYTES;
        #pragma unroll
        for (int r = 0; r < 4; r++) {            // 128 A rows
            int row = r * 32 + lrow;
            uint32_t sw = swz(row * 128 + lch * 16);
            cp_async16(sa + sw, Asrc + (size_t)row * lda + lch * 8);
        }
        #pragma unroll
        for (int r = 0; r < 8; r++) {            // 256 B rows
            int row = r * 32 + lrow;
            uint32_t sw = swz(row * 128 + lch * 16);
            cp_async16(sb + sw, Bsrc + (size_t)row * ldb + lch * 8);
        }
        CP_COMMIT();
    };

    float acc[4][8][4];
    #pragma unroll
    for (int i = 0; i < 4; i++)
        #pragma unroll
        for (int j = 0; j < 8; j++)
            #pragma unroll
            for (int e = 0; e < 4; e++) acc[i][j][e] = 0.f;

    // ldmatrix per-lane address components
    const int a_row_l = ((lane >> 3) & 1) * 8 + (lane & 7);
    const int a_col_l = ((lane >> 4) & 1) * 16;           // bytes
    const int b_row_l = ((lane >> 4) & 1) * 8 + (lane & 7);
    const int b_col_l = ((lane >> 3) & 1) * 16;           // bytes

    // prologue
    #pragma unroll
    for (int i = 0; i < STAGES; i++) load_stage(i, i);

    int s = 0;
    for (int kc = 0; kc < NK; kc++) {
        CP_WAIT(STAGES - 1);
        __syncthreads();

        const uint32_t sa = sbase + s * STAGE_BYTES;
        const uint32_t sb = sa + TILE_A_BYTES;

        #pragma unroll
        for (int k16 = 0; k16 < 4; k16++) {
            uint32_t a[4][4];
            uint32_t b[8][2];
            #pragma unroll
            for (int mt = 0; mt < 4; mt++) {
                uint32_t off = (uint32_t)(wm + mt * 16 + a_row_l) * 128 + k16 * 32 + a_col_l;
                ldsm_x4(a[mt][0], a[mt][1], a[mt][2], a[mt][3], sa + swz(off));
            }
            #pragma unroll
            for (int nt2 = 0; nt2 < 4; nt2++) {
                uint32_t off = (uint32_t)(wn + nt2 * 16 + b_row_l) * 128 + k16 * 32 + b_col_l;
                uint32_t r0, r1, r2, r3;
                ldsm_x4(r0, r1, r2, r3, sb + swz(off));
                b[nt2 * 2 + 0][0] = r0; b[nt2 * 2 + 0][1] = r1;
                b[nt2 * 2 + 1][0] = r2; b[nt2 * 2 + 1][1] = r3;
            }
            #pragma unroll
            for (int mt = 0; mt < 4; mt++)
                #pragma unroll
                for (int nt = 0; nt < 8; nt++)
                    mma16816(acc[mt][nt], a[mt], b[nt]);
        }

        __syncthreads();
        if (kc + STAGES < NK) load_stage(kc + STAGES, s);
        s++;
        if (s == STAGES) s = 0;
    }

    // ---------------- epilogue ----------------
    const int erow = lane >> 2;         // 0..7
    const int ecol = (lane & 3) * 2;    // 0,2,4,6

    #pragma unroll
    for (int mt = 0; mt < 4; mt++) {
        #pragma unroll
        for (int h = 0; h < 2; h++) {   // row / row+8 halves of the m16 tile
            const int gm = m0 + wm + mt * 16 + h * 8 + erow;
            float brow = (bias_mode == 2) ? bias[gm] : 0.f;
            #pragma unroll
            for (int nt = 0; nt < 8; nt++) {
                const int gn = n0 + wn + nt * 8 + ecol;
                float x0 = acc[mt][nt][h * 2 + 0] * alpha;
                float x1 = acc[mt][nt][h * 2 + 1] * alpha;
                if (bias_mode == 1) { x0 += bias[gn]; x1 += bias[gn + 1]; }
                else if (bias_mode == 2) { x0 += brow; x1 += brow; }
                if (Cf) {
                    float2 v; v.x = x0; v.y = x1;
                    *(float2*)(Cf + bz * batCf + (size_t)gm * ldc + gn) = v;
                } else {
                    __nv_bfloat16 h0 = __float2bfloat16(x0);
                    __nv_bfloat16 h1 = __float2bfloat16(x1);
                    __nv_bfloat16 l0 = __float2bfloat16(x0 - __bfloat162float(h0));
                    __nv_bfloat16 l1 = __float2bfloat16(x1 - __bfloat162float(h1));
                    union { uint32_t u; __nv_bfloat16 hh[2]; } ph, pl;
                    ph.hh[0] = h0; ph.hh[1] = h1;
                    pl.hh[0] = l0; pl.hh[1] = l1;
                    *(uint32_t*)(Chi + bz * batCb + (size_t)gm * ldc + gn) = ph.u;
                    *(uint32_t*)(Clo + bz * batCb + (size_t)gm * ldc + gn) = pl.u;
                }
            }
        }
    }
}

// ---------------- elementwise kernels ----------------
__global__ __launch_bounds__(256) void split_fp32(
    const float* __restrict__ x, __nv_bfloat16* __restrict__ hi,
    __nv_bfloat16* __restrict__ lo, size_t n4)
{
    size_t i = ((size_t)blockIdx.x * blockDim.x + threadIdx.x);
    if (i >= n4) return;
    float4 v = *(const float4*)(x + i * 4);
    float vv[4] = {v.x, v.y, v.z, v.w};
    union { uint2 u; __nv_bfloat16 h[4]; } ph, pl;
    #pragma unroll
    for (int e = 0; e < 4; e++) {
        __nv_bfloat16 h16 = __float2bfloat16(vv[e]);
        ph.h[e] = h16;
        pl.h[e] = __float2bfloat16(vv[e] - __bfloat162float(h16));
    }
    *(uint2*)(hi + i * 4) = ph.u;
    *(uint2*)(lo + i * 4) = pl.u;
}

// softmax over rows of 2048 fp32, in-place, plus bf16 hi/lo split output.
__global__ __launch_bounds__(256) void softmax_split(
    float* __restrict__ P, __nv_bfloat16* __restrict__ Phi, __nv_bfloat16* __restrict__ Plo)
{
    const size_t row = blockIdx.x;
    float* p = P + row * (size_t)N_;
    __nv_bfloat16* ph = Phi + row * (size_t)N_;
    __nv_bfloat16* pl = Plo + row * (size_t)N_;
    const int tid = threadIdx.x;
    const int lane = tid & 31;
    const int warp = tid >> 5;

    float vals[8];
    float m = -INFINITY;
    #pragma unroll
    for (int i = 0; i < 8; i++) {
        vals[i] = p[tid + i * 256];
        m = fmaxf(m, vals[i]);
    }
    __shared__ float redmax[8], redsum[8];
    #pragma unroll
    for (int off = 16; off > 0; off >>= 1)
        m = fmaxf(m, __shfl_xor_sync(0xffffffffu, m, off));
    if (lane == 0) redmax[warp] = m;
    __syncthreads();
    float rowmax = redmax[0];
    #pragma unroll
    for (int w = 1; w < 8; w++) rowmax = fmaxf(rowmax, redmax[w]);

    float sum = 0.f;
    #pragma unroll
    for (int i = 0; i < 8; i++) {
        vals[i] = expf(vals[i] - rowmax);
        sum += vals[i];
    }
    #pragma unroll
    for (int off = 16; off > 0; off >>= 1)
        sum += __shfl_xor_sync(0xffffffffu, sum, off);
    if (lane == 0) redsum[warp] = sum;
    __syncthreads();
    float total = 0.f;
    #pragma unroll
    for (int w = 0; w < 8; w++) total += redsum[w];
    float inv = 1.f / total;

    #pragma unroll
    for (int i = 0; i < 8; i++) {
        float v = vals[i] * inv;
        p[tid + i * 256] = v;
        __nv_bfloat16 hi = __float2bfloat16(v);
        ph[tid + i * 256] = hi;
        pl[tid + i * 256] = __float2bfloat16(v - __bfloat162float(hi));
    }
}

// ---------------- launch ----------------
extern "C" void kernel_launch(void* const* d_in, const int* in_sizes, int n_in,
                              void* d_out, int out_size)
{
    const float* h  = (const float*)d_in[0];
    const float* Wq = (const float*)d_in[1];
    const float* bq = (const float*)d_in[2];
    const float* Wk = (const float*)d_in[3];
    const float* bk = (const float*)d_in[4];
    const float* Wv = (const float*)d_in[5];
    const float* bv = (const float*)d_in[6];

    float* out  = (float*)d_out;                 // [B,N,C]
    float* attn = out + (size_t)B_ * N_ * C_;    // [B,N,N]

    __nv_bfloat16 *h_hi, *h_lo, *Wq_hi, *Wq_lo, *Wk_hi, *Wk_lo, *Wv_hi, *Wv_lo;
    __nv_bfloat16 *Q_hi, *Q_lo, *K_hi, *K_lo, *VT_hi, *VT_lo, *P_hi, *P_lo;
    cudaGetSymbolAddress((void**)&h_hi, g_h_hi);   cudaGetSymbolAddress((void**)&h_lo, g_h_lo);
    cudaGetSymbolAddress((void**)&Wq_hi, g_Wq_hi); cudaGetSymbolAddress((void**)&Wq_lo, g_Wq_lo);
    cudaGetSymbolAddress((void**)&Wk_hi, g_Wk_hi); cudaGetSymbolAddress((void**)&Wk_lo, g_Wk_lo);
    cudaGetSymbolAddress((void**)&Wv_hi, g_Wv_hi); cudaGetSymbolAddress((void**)&Wv_lo, g_Wv_lo);
    cudaGetSymbolAddress((void**)&Q_hi, g_Q_hi);   cudaGetSymbolAddress((void**)&Q_lo, g_Q_lo);
    cudaGetSymbolAddress((void**)&K_hi, g_K_hi);   cudaGetSymbolAddress((void**)&K_lo, g_K_lo);
    cudaGetSymbolAddress((void**)&VT_hi, g_VT_hi); cudaGetSymbolAddress((void**)&VT_lo, g_VT_lo);
    cudaGetSymbolAddress((void**)&P_hi, g_P_hi);   cudaGetSymbolAddress((void**)&P_lo, g_P_lo);

    cudaFuncSetAttribute(gemm_bf16x3, cudaFuncAttributeMaxDynamicSharedMemorySize, SMEM_GEMM);

    // 1) splits
    {
        size_t nh4 = (size_t)M_TOT * C_ / 4;
        split_fp32<<<(unsigned)(nh4 / 256), 256>>>(h, h_hi, h_lo, nh4);
        size_t nw4 = (size_t)C_ * C_ / 4;
        split_fp32<<<(unsigned)(nw4 / 256), 256>>>(Wq, Wq_hi, Wq_lo, nw4);
        split_fp32<<<(unsigned)(nw4 / 256), 256>>>(Wk, Wk_hi, Wk_lo, nw4);
        split_fp32<<<(unsigned)(nw4 / 256), 256>>>(Wv, Wv_hi, Wv_lo, nw4);
    }

    dim3 blk(256);

    // 2) Q/K projections: [8192,1024] x [1024,1024]^T -> bf16 hi/lo
    {
        dim3 g(C_ / BN_, M_TOT / BM_, 1);
        gemm_bf16x3<<<g, blk, SMEM_GEMM>>>(
            h_hi, h_lo, Wq_hi, Wq_lo, C_, C_, 0, 0, C_,
            nullptr, 0, C_, Q_hi, Q_lo, 0, 1.0f, bq, 1);
        gemm_bf16x3<<<g, blk, SMEM_GEMM>>>(
            h_hi, h_lo, Wk_hi, Wk_lo, C_, C_, 0, 0, C_,
            nullptr, 0, C_, K_hi, K_lo, 0, 1.0f, bk, 1);
    }
    // 3) V^T = Wv @ h^T + bv (row bias) -> [C_, M_TOT] bf16 hi/lo
    {
        dim3 g(M_TOT / BN_, C_ / BM_, 1);
        gemm_bf16x3<<<g, blk, SMEM_GEMM>>>(
            Wv_hi, Wv_lo, h_hi, h_lo, C_, C_, 0, 0, C_,
            nullptr, 0, M_TOT, VT_hi, VT_lo, 0, 1.0f, bv, 2);
    }
    // 4) scores = (Q @ K^T) / 32 -> fp32 attn (per batch)
    {
        dim3 g(N_ / BN_, N_ / BM_, B_);
        gemm_bf16x3<<<g, blk, SMEM_GEMM>>>(
            Q_hi, Q_lo, K_hi, K_lo, C_, C_,
            (long long)N_ * C_, (long long)N_ * C_, C_,
            attn, (long long)N_ * N_, N_,
            nullptr, nullptr, 0, 1.0f / 32.0f, nullptr, 0);
    }
    // 5) softmax (in place) + bf16 split
    softmax_split<<<B_ * N_, 256>>>(attn, P_hi, P_lo);

    // 6) out = P @ (V^T)^T (per batch: M=2048, N=1024, K=2048)
    {
        dim3 g(C_ / BN_, N_ / BM_, B_);
        gemm_bf16x3<<<g, blk, SMEM_GEMM>>>(
            P_hi, P_lo, VT_hi, VT_lo, N_, M_TOT,
            (long long)N_ * N_, (long long)N_, N_,
            out, (long long)N_ * C_, C_,
            nullptr, nullptr, 0, 1.0f, nullptr, 0);
    }
}